// round 1
// baseline (speedup 1.0000x reference)
#include <cuda_runtime.h>
#include <math.h>

#define BB 4
#define TT 2048
#define DD 1024
#define KQ 32
#define NT (BB*TT)      // 8192 rows total
#define KTOP 4

// Scratch (no allocations allowed)
__device__ float g_Q[NT*KQ];
__device__ float g_K[NT*KQ];
__device__ __align__(16) int g_idx[NT*KTOP];

// ---------------------------------------------------------------------------
// Kernel 1: fused Q/K projection. [8192,1024] x [1024,64] (cols 0..31 = Q, 32..63 = K)
// 64 rows per block, 256 threads, 4x4 register microtile per thread.
// ---------------------------------------------------------------------------
__global__ __launch_bounds__(256) void proj_kernel(
    const float* __restrict__ x, const float* __restrict__ Wq,
    const float* __restrict__ bq, const float* __restrict__ Wk,
    const float* __restrict__ bk)
{
    __shared__ float Xs[64][68];   // +4 pad: breaks stride-64 bank conflicts, keeps 16B align
    __shared__ float Ws[64][64];   // Ws[kk][col]

    const int tid  = threadIdx.x;
    const int row0 = blockIdx.x * 64;
    const int tr   = tid >> 4;     // 0..15
    const int tc   = tid & 15;     // 0..15

    float acc[4][4];
    #pragma unroll
    for (int i = 0; i < 4; i++)
        #pragma unroll
        for (int j = 0; j < 4; j++) acc[i][j] = 0.0f;

    for (int k0 = 0; k0 < DD; k0 += 64) {
        // Load X tile: 64 rows x 64 cols = 1024 float4
        #pragma unroll
        for (int l = 0; l < 4; l++) {
            int f  = tid + l * 256;
            int r  = f >> 4;
            int c4 = f & 15;
            *(float4*)&Xs[r][c4 * 4] =
                *(const float4*)&x[(size_t)(row0 + r) * DD + k0 + c4 * 4];
        }
        // Load W tile transposed: Ws[kk][col] = W[col][k0+kk]
        {
            int col = tid & 63;
            int kg  = tid >> 6;    // 0..3, each covers 16 kk
            const float* Wrow = (col < KQ) ? &Wq[col * DD] : &Wk[(col - KQ) * DD];
            #pragma unroll
            for (int l = 0; l < 4; l++) {
                int kk = kg * 16 + l * 4;
                float4 w = *(const float4*)&Wrow[k0 + kk];
                Ws[kk + 0][col] = w.x;
                Ws[kk + 1][col] = w.y;
                Ws[kk + 2][col] = w.z;
                Ws[kk + 3][col] = w.w;
            }
        }
        __syncthreads();

        #pragma unroll
        for (int k4 = 0; k4 < 16; k4++) {
            float4 xv[4];
            #pragma unroll
            for (int i = 0; i < 4; i++)
                xv[i] = *(const float4*)&Xs[tr * 4 + i][k4 * 4];
            #pragma unroll
            for (int m = 0; m < 4; m++) {
                float4 wv = *(const float4*)&Ws[k4 * 4 + m][tc * 4];
                float xm[4] = { ((const float*)&xv[0])[m], ((const float*)&xv[1])[m],
                                ((const float*)&xv[2])[m], ((const float*)&xv[3])[m] };
                float wm[4] = { wv.x, wv.y, wv.z, wv.w };
                #pragma unroll
                for (int i = 0; i < 4; i++)
                    #pragma unroll
                    for (int j = 0; j < 4; j++)
                        acc[i][j] = fmaf(xm[i], wm[j], acc[i][j]);
            }
        }
        __syncthreads();
    }

    // Epilogue: add bias, split into Q and K scratch
    #pragma unroll
    for (int i = 0; i < 4; i++) {
        int r = row0 + tr * 4 + i;
        #pragma unroll
        for (int j = 0; j < 4; j++) {
            int c = tc * 4 + j;
            float v = acc[i][j] + ((c < KQ) ? bq[c] : bk[c - KQ]);
            if (c < KQ) g_Q[r * KQ + c] = v;
            else        g_K[r * KQ + (c - KQ)] = v;
        }
    }
}

// ---------------------------------------------------------------------------
// Kernel 2: similarity + streaming top-4 per row.
// 64 t-rows per block (same batch), 256 threads, 4 threads per row partition s.
// ---------------------------------------------------------------------------
__global__ __launch_bounds__(256) void sim_topk_kernel()
{
    __shared__ float Ks[128][36];   // 128 keys x 32 dims, +4 pad
    __shared__ float Mv[256 * 4];
    __shared__ int   Mi[256 * 4];

    const int tid  = threadIdx.x;
    const int row0 = blockIdx.x * 64;
    const int b    = row0 / TT;
    const int rl   = tid >> 2;      // 0..63 local row
    const int sub  = tid & 3;       // s partition
    const int trow = row0 + rl;

    float q[KQ];
    #pragma unroll
    for (int i = 0; i < KQ; i += 4) {
        float4 v = *(const float4*)&g_Q[trow * KQ + i];
        q[i] = v.x; q[i + 1] = v.y; q[i + 2] = v.z; q[i + 3] = v.w;
    }

    float v0 = -INFINITY, v1 = -INFINITY, v2 = -INFINITY, v3 = -INFINITY;
    int   i0 = 0, i1 = 0, i2 = 0, i3 = 0;

    const float* Kb = &g_K[b * TT * KQ];

    for (int s0 = 0; s0 < TT; s0 += 128) {
        // stage K tile: 128 x 32 = 1024 float4
        #pragma unroll
        for (int l = 0; l < 4; l++) {
            int f = tid + l * 256;
            int r = f >> 3;          // 8 float4 per key
            int c = f & 7;
            *(float4*)&Ks[r][c * 4] =
                *(const float4*)&Kb[(s0 + r) * KQ + c * 4];
        }
        __syncthreads();

        for (int sl = sub; sl < 128; sl += 4) {
            float a0 = 0.0f, a1 = 0.0f;
            #pragma unroll
            for (int k4 = 0; k4 < 8; k4++) {
                float4 kk = *(const float4*)&Ks[sl][k4 * 4];
                a0 = fmaf(q[k4 * 4 + 0], kk.x, a0);
                a1 = fmaf(q[k4 * 4 + 1], kk.y, a1);
                a0 = fmaf(q[k4 * 4 + 2], kk.z, a0);
                a1 = fmaf(q[k4 * 4 + 3], kk.w, a1);
            }
            float v = a0 + a1;
            int  si = s0 + sl;
            if (v > v3) {
                if (v > v1) {
                    v3 = v2; i3 = i2; v2 = v1; i2 = i1;
                    if (v > v0) { v1 = v0; i1 = i0; v0 = v; i0 = si; }
                    else        { v1 = v;  i1 = si; }
                } else {
                    if (v > v2) { v3 = v2; i3 = i2; v2 = v; i2 = si; }
                    else        { v3 = v;  i3 = si; }
                }
            }
        }
        __syncthreads();
    }

    // merge 4 partial top-4 lists per row
    Mv[tid * 4 + 0] = v0; Mi[tid * 4 + 0] = i0;
    Mv[tid * 4 + 1] = v1; Mi[tid * 4 + 1] = i1;
    Mv[tid * 4 + 2] = v2; Mi[tid * 4 + 2] = i2;
    Mv[tid * 4 + 3] = v3; Mi[tid * 4 + 3] = i3;
    __syncthreads();

    if (sub == 0) {
        float cv[16]; int ci[16];
        #pragma unroll
        for (int k = 0; k < 16; k++) {
            cv[k] = Mv[tid * 4 + k];   // tid = rl*4 -> contiguous 16 entries for this row
            ci[k] = Mi[tid * 4 + k];
        }
        int outbase = trow * KTOP;
        #pragma unroll
        for (int p = 0; p < KTOP; p++) {
            int best = 0;
            #pragma unroll
            for (int k = 1; k < 16; k++)
                if (cv[k] > cv[best]) best = k;
            g_idx[outbase + p] = ci[best];
            cv[best] = -INFINITY;
        }
    }
}

// ---------------------------------------------------------------------------
// Kernel 3: gather 4 neighbor rows + mean. One block per (b,t) row.
// ---------------------------------------------------------------------------
__global__ __launch_bounds__(256) void gather_kernel(
    const float* __restrict__ x, float* __restrict__ out)
{
    const int row = blockIdx.x;
    const int b   = row >> 11;     // row / TT
    const int4 iv = *(const int4*)&g_idx[row * 4];

    const float4* xb = (const float4*)(x + (size_t)b * TT * DD);
    const float4* r0 = xb + (size_t)iv.x * (DD / 4);
    const float4* r1 = xb + (size_t)iv.y * (DD / 4);
    const float4* r2 = xb + (size_t)iv.z * (DD / 4);
    const float4* r3 = xb + (size_t)iv.w * (DD / 4);

    const int c = threadIdx.x;     // 256 threads x float4 = 1024 floats
    float4 a = r0[c], bq4 = r1[c], cq = r2[c], dq = r3[c];
    float4 o;
    o.x = (a.x + bq4.x + cq.x + dq.x) * 0.25f;
    o.y = (a.y + bq4.y + cq.y + dq.y) * 0.25f;
    o.z = (a.z + bq4.z + cq.z + dq.z) * 0.25f;
    o.w = (a.w + bq4.w + cq.w + dq.w) * 0.25f;
    ((float4*)out)[(size_t)row * (DD / 4) + c] = o;
}

// ---------------------------------------------------------------------------
extern "C" void kernel_launch(void* const* d_in, const int* in_sizes, int n_in,
                              void* d_out, int out_size)
{
    const float* x  = (const float*)d_in[0];
    const float* Wq = (const float*)d_in[1];
    const float* bq = (const float*)d_in[2];
    const float* Wk = (const float*)d_in[3];
    const float* bk = (const float*)d_in[4];
    float* out = (float*)d_out;

    proj_kernel<<<NT / 64, 256>>>(x, Wq, bq, Wk, bk);
    sim_topk_kernel<<<NT / 64, 256>>>();
    gather_kernel<<<NT, 256>>>(x, out);
}